// round 6
// baseline (speedup 1.0000x reference)
#include <cuda_runtime.h>
#include <math.h>

#define BB 128
#define TT 512
#define HH 1024
#define SS 128
#define KK 64
#define HIDV 512
#define DD 1152
#define G3 3072
#define GRID 128
#define NTHR 256

// ---------------- scratch (device globals; no allocation allowed) ----------
__device__ float g_Mse[KK * G3];                    // E @ W_ih_e^T  [k][j]
__device__ float g_Gx[(size_t)TT * BB * G3];        // [t][b][3H]
__device__ float g_hbuf[2][BB * HH];                // double-buffered hidden
__device__ float g_state[BB * KK];                  // current soft state
__device__ float g_a1[BB * HIDV];                   // tanh(h@W1^T+b1)
__device__ unsigned g_cnt;
__device__ unsigned g_epoch;

// ---------------- init: h=0, state=initial_state, barrier reset ------------
__global__ void k_init(const float* __restrict__ init_state) {
    int idx = blockIdx.x * blockDim.x + threadIdx.x;
    if (idx < BB * HH) g_hbuf[0][idx] = 0.0f;
    if (idx < BB * KK) g_state[idx] = init_state[idx];
    if (idx == 0) { g_cnt = 0u; g_epoch = 0u; }
}

// ---------------- Mse[k][j] = sum_s E[k][s] * W_ih[j][H+s] -----------------
__global__ void k_mse(const float* __restrict__ E, const float* __restrict__ Wih) {
    int j = blockIdx.x;                 // 0..3071
    __shared__ float w[SS];
    for (int s = threadIdx.x; s < SS; s += 64)
        w[s] = Wih[(size_t)j * DD + HH + s];
    __syncthreads();
    int k = threadIdx.x;                // 0..63
    float acc = 0.0f;
#pragma unroll 8
    for (int s = 0; s < SS; s++) acc += E[k * SS + s] * w[s];
    g_Mse[k * G3 + j] = acc;
}

// ---------------- Gx = contexts @ W_ih[:, :H]^T + b_ih ---------------------
// classic 128x128x8 SGEMM, 256 threads, 8x8 microtile
__global__ void k_gx(const float* __restrict__ ctx, const float* __restrict__ W,
                     const float* __restrict__ bih) {
    __shared__ float As[8][128];
    __shared__ float Bs[8][128];
    int tid = threadIdx.x;
    int m0 = blockIdx.y * 128, j0 = blockIdx.x * 128;
    int row = tid >> 1, c = (tid & 1) * 4;
    int tx = tid & 15, ty = tid >> 4;
    float acc[8][8];
#pragma unroll
    for (int i = 0; i < 8; i++)
#pragma unroll
        for (int j = 0; j < 8; j++) acc[i][j] = 0.0f;

    const float* aptr = ctx + (size_t)(m0 + row) * HH + c;
    const float* bptr = W + (size_t)(j0 + row) * DD + c;

    for (int k0 = 0; k0 < HH; k0 += 8) {
        float4 av = *(const float4*)(aptr + k0);
        float4 bv = *(const float4*)(bptr + k0);
        __syncthreads();
        As[c + 0][row] = av.x; As[c + 1][row] = av.y;
        As[c + 2][row] = av.z; As[c + 3][row] = av.w;
        Bs[c + 0][row] = bv.x; Bs[c + 1][row] = bv.y;
        Bs[c + 2][row] = bv.z; Bs[c + 3][row] = bv.w;
        __syncthreads();
#pragma unroll
        for (int k = 0; k < 8; k++) {
            float a[8], b[8];
            *(float4*)&a[0] = *(const float4*)&As[k][ty * 8];
            *(float4*)&a[4] = *(const float4*)&As[k][ty * 8 + 4];
            *(float4*)&b[0] = *(const float4*)&Bs[k][tx * 8];
            *(float4*)&b[4] = *(const float4*)&Bs[k][tx * 8 + 4];
#pragma unroll
            for (int i = 0; i < 8; i++)
#pragma unroll
                for (int j = 0; j < 8; j++) acc[i][j] += a[i] * b[j];
        }
    }
#pragma unroll
    for (int i = 0; i < 8; i++) {
        int m = m0 + ty * 8 + i;
        int bb = m >> 9;          // m / T
        int t  = m & 511;         // m % T
        float* dst = g_Gx + ((size_t)t * BB + bb) * G3 + j0 + tx * 8;
#pragma unroll
        for (int j = 0; j < 8; j++)
            dst[j] = acc[i][j] + bih[j0 + tx * 8 + j];
    }
}

// ---------------- software grid barrier (all GRID blocks co-resident) ------
__device__ __forceinline__ void gsync(unsigned target) {
    __syncthreads();
    if (threadIdx.x == 0) {
        __threadfence();
        if (atomicAdd(&g_cnt, 1u) == GRID - 1u) {
            g_cnt = 0u;
            __threadfence();
            atomicExch(&g_epoch, target);
        } else {
            while (*(volatile unsigned*)&g_epoch < target) { __nanosleep(64); }
        }
        __threadfence();
    }
    __syncthreads();
}

// ---------------- persistent sequence kernel --------------------------------
// 128 blocks x 256 threads, 3 phases per timestep, 3 grid barriers per step.
__global__ void __launch_bounds__(NTHR, 2)
k_seq(const float* __restrict__ Whh, const float* __restrict__ bhh,
      const float* __restrict__ W1, const float* __restrict__ b1,
      const float* __restrict__ W2, const float* __restrict__ b2,
      float* __restrict__ out)
{
    __shared__ float sh[2048];          // 8 KB, overlaid per phase
    const int tid = threadIdx.x;
    const int blk = blockIdx.x;
    unsigned bar = 1;

    // Phase A tile: 32 batch x 32 hidden-cols, thread microtile 2x2 (x3 gates)
    const int a_b0 = (blk >> 5) * 32;
    const int a_i0 = (blk & 31) * 32;
    const int ty = tid >> 4;            // 0..15 (batch pairs)
    const int tx = tid & 15;            // 0..15 (col pairs)
    const int lr = tid >> 2;            // loader row (tid<128 -> 0..31)
    const int lc = (tid & 3) * 4;       // loader k offset

    for (int t = 0; t < TT; t++) {
        const float* hcur = g_hbuf[t & 1];
        float* hnxt = g_hbuf[(t & 1) ^ 1];

        // ================= Phase A: recurrent GEMM + gates =================
        float aR[2][2] = {}, aZ[2][2] = {}, aNH[2][2] = {}, aNI[2][2] = {};

        // hidden part: k in [0,1024) over (h, Whh)
        for (int k0 = 0; k0 < HH; k0 += 16) {
            if (tid < 128) {
                float4 v = *(const float4*)&hcur[(a_b0 + lr) * HH + k0 + lc];
                sh[(lc + 0) * 32 + lr] = v.x; sh[(lc + 1) * 32 + lr] = v.y;
                sh[(lc + 2) * 32 + lr] = v.z; sh[(lc + 3) * 32 + lr] = v.w;
            }
            for (int q = tid; q < 384; q += NTHR) {      // 96 rows x 4 float4s
                int row = q >> 2, c = (q & 3) * 4;
                int jr = a_i0 + (row < 32 ? row : row < 64 ? 1024 + row - 32
                                                           : 2048 + row - 64);
                float4 w = *(const float4*)&Whh[(size_t)jr * HH + k0 + c];
                sh[512 + (c + 0) * 96 + row] = w.x;
                sh[512 + (c + 1) * 96 + row] = w.y;
                sh[512 + (c + 2) * 96 + row] = w.z;
                sh[512 + (c + 3) * 96 + row] = w.w;
            }
            __syncthreads();
#pragma unroll
            for (int k = 0; k < 16; k++) {
                float2 a  = *(float2*)&sh[k * 32 + ty * 2];
                float2 br = *(float2*)&sh[512 + k * 96 + tx * 2];
                float2 bz = *(float2*)&sh[512 + k * 96 + 32 + tx * 2];
                float2 bn = *(float2*)&sh[512 + k * 96 + 64 + tx * 2];
                aR[0][0] += a.x * br.x; aR[0][1] += a.x * br.y;
                aR[1][0] += a.y * br.x; aR[1][1] += a.y * br.y;
                aZ[0][0] += a.x * bz.x; aZ[0][1] += a.x * bz.y;
                aZ[1][0] += a.y * bz.x; aZ[1][1] += a.y * bz.y;
                aNH[0][0] += a.x * bn.x; aNH[0][1] += a.x * bn.y;
                aNH[1][0] += a.y * bn.x; aNH[1][1] += a.y * bn.y;
            }
            __syncthreads();
        }

        // state part: k in [0,64) over (state, Mse)
        for (int k0 = 0; k0 < KK; k0 += 16) {
            if (tid < 128) {
                float4 v = *(const float4*)&g_state[(a_b0 + lr) * KK + k0 + lc];
                sh[(lc + 0) * 32 + lr] = v.x; sh[(lc + 1) * 32 + lr] = v.y;
                sh[(lc + 2) * 32 + lr] = v.z; sh[(lc + 3) * 32 + lr] = v.w;
            }
            for (int q = tid; q < 384; q += NTHR) {      // 16 k x 24 float4s
                int k = q / 24, cc = (q % 24) * 4;
                int jm = a_i0 + (cc < 32 ? cc : cc < 64 ? 1024 + cc - 32
                                                        : 2048 + cc - 64);
                float4 m = *(const float4*)&g_Mse[(size_t)(k0 + k) * G3 + jm];
                sh[512 + k * 96 + cc + 0] = m.x;
                sh[512 + k * 96 + cc + 1] = m.y;
                sh[512 + k * 96 + cc + 2] = m.z;
                sh[512 + k * 96 + cc + 3] = m.w;
            }
            __syncthreads();
#pragma unroll
            for (int k = 0; k < 16; k++) {
                float2 a  = *(float2*)&sh[k * 32 + ty * 2];
                float2 br = *(float2*)&sh[512 + k * 96 + tx * 2];
                float2 bz = *(float2*)&sh[512 + k * 96 + 32 + tx * 2];
                float2 bn = *(float2*)&sh[512 + k * 96 + 64 + tx * 2];
                aR[0][0] += a.x * br.x; aR[0][1] += a.x * br.y;
                aR[1][0] += a.y * br.x; aR[1][1] += a.y * br.y;
                aZ[0][0] += a.x * bz.x; aZ[0][1] += a.x * bz.y;
                aZ[1][0] += a.y * bz.x; aZ[1][1] += a.y * bz.y;
                aNI[0][0] += a.x * bn.x; aNI[0][1] += a.x * bn.y;
                aNI[1][0] += a.y * bn.x; aNI[1][1] += a.y * bn.y;
            }
            __syncthreads();
        }

        // gates epilogue -> h_new
        {
            const float* gx = g_Gx + (size_t)t * BB * G3;
#pragma unroll
            for (int i2 = 0; i2 < 2; i2++) {
                int b = a_b0 + ty * 2 + i2;
                const float* gxb = gx + (size_t)b * G3;
                const float* hb = &hcur[b * HH];
                float* hnb = &hnxt[b * HH];
#pragma unroll
                for (int j2 = 0; j2 < 2; j2++) {
                    int ii = a_i0 + tx * 2 + j2;
                    float Sr = aR[i2][j2] + gxb[ii] + bhh[ii];
                    float Sz = aZ[i2][j2] + gxb[1024 + ii] + bhh[1024 + ii];
                    float An = aNI[i2][j2] + gxb[2048 + ii];
                    float Hn = aNH[i2][j2] + bhh[2048 + ii];
                    float r = 1.0f / (1.0f + expf(-Sr));
                    float z = 1.0f / (1.0f + expf(-Sz));
                    float n = tanhf(An + r * Hn);
                    hnb[ii] = (1.0f - z) * n + z * hb[ii];
                }
            }
        }
        gsync(bar++);

        // ================= Phase B: a1 = tanh(h_new @ W1^T + b1) ===========
        {
            const int b_b0 = (blk >> 5) * 32;
            const int b_o0 = (blk & 31) * 16;
            const int bty = tid >> 3;   // 0..31 (batch)
            const int btx = tid & 7;    // 0..7  (output pairs)
            float c0 = 0.0f, c1 = 0.0f;
            for (int k0 = 0; k0 < HH; k0 += 16) {
                if (tid < 128) {
                    float4 v = *(const float4*)&hnxt[(b_b0 + lr) * HH + k0 + lc];
                    sh[(lc + 0) * 32 + lr] = v.x; sh[(lc + 1) * 32 + lr] = v.y;
                    sh[(lc + 2) * 32 + lr] = v.z; sh[(lc + 3) * 32 + lr] = v.w;
                }
                if (tid < 64) {
                    int row = tid >> 2, c = (tid & 3) * 4;
                    float4 w = *(const float4*)&W1[(size_t)(b_o0 + row) * HH + k0 + c];
                    sh[512 + (c + 0) * 16 + row] = w.x;
                    sh[512 + (c + 1) * 16 + row] = w.y;
                    sh[512 + (c + 2) * 16 + row] = w.z;
                    sh[512 + (c + 3) * 16 + row] = w.w;
                }
                __syncthreads();
#pragma unroll
                for (int k = 0; k < 16; k++) {
                    float a = sh[k * 32 + bty];
                    float2 w = *(float2*)&sh[512 + k * 16 + btx * 2];
                    c0 += a * w.x; c1 += a * w.y;
                }
                __syncthreads();
            }
            int b = b_b0 + bty, o = b_o0 + btx * 2;
            g_a1[b * HIDV + o]     = tanhf(c0 + b1[o]);
            g_a1[b * HIDV + o + 1] = tanhf(c1 + b1[o + 1]);
        }
        gsync(bar++);

        // ================= Phase C: logits + softmax state =================
        {
            int b = blk;                    // 128 blocks == 128 batches
            for (int i = tid; i < HIDV; i += NTHR) sh[i] = g_a1[b * HIDV + i];
            __syncthreads();
            int k = tid & 63, q = tid >> 6;
            const float* w = W2 + (size_t)k * HIDV + q * 128;
            const float* a = sh + q * 128;
            float p = 0.0f;
#pragma unroll 16
            for (int i = 0; i < 128; i++) p += a[i] * w[i];
            sh[512 + tid] = p;
            __syncthreads();
            if (tid < KK) {
                float lg = sh[512 + tid] + sh[512 + tid + 64] +
                           sh[512 + tid + 128] + sh[512 + tid + 192] + b2[tid];
                out[((size_t)b * TT + t) * KK + tid] = lg;   // raw logits
                sh[768 + tid] = fminf(fmaxf(lg, -10.0f), 10.0f);
            }
            __syncthreads();
            if (tid < 32) {
                float x0 = sh[768 + tid], x1 = sh[768 + tid + 32];
                float m = fmaxf(x0, x1);
#pragma unroll
                for (int o = 16; o; o >>= 1) m = fmaxf(m, __shfl_xor_sync(0xffffffffu, m, o));
                float e0 = expf(x0 - m), e1 = expf(x1 - m);
                float s = e0 + e1;
#pragma unroll
                for (int o = 16; o; o >>= 1) s += __shfl_xor_sync(0xffffffffu, s, o);
                float inv = 1.0f / s;
                g_state[b * KK + tid]      = e0 * inv;
                g_state[b * KK + tid + 32] = e1 * inv;
            }
        }
        gsync(bar++);
    }
}

// ---------------- host launch -----------------------------------------------
extern "C" void kernel_launch(void* const* d_in, const int* in_sizes, int n_in,
                              void* d_out, int out_size) {
    const float* ctx  = (const float*)d_in[0];   // [B,T,H]
    const float* init = (const float*)d_in[1];   // [B,K]
    const float* E    = (const float*)d_in[2];   // [K,S]
    const float* Wih  = (const float*)d_in[3];   // [3H,D]
    const float* Whh  = (const float*)d_in[4];   // [3H,H]
    const float* bih  = (const float*)d_in[5];   // [3H]
    const float* bhh  = (const float*)d_in[6];   // [3H]
    const float* W1   = (const float*)d_in[7];   // [HID,H]
    const float* b1   = (const float*)d_in[8];   // [HID]
    const float* W2   = (const float*)d_in[9];   // [K,HID]
    const float* b2   = (const float*)d_in[10];  // [K]
    float* out = (float*)d_out;                  // [B,T,K] fp32

    k_init<<<512, 256>>>(init);
    k_mse<<<G3, 64>>>(E, Wih);
    k_gx<<<dim3(G3 / 128, (BB * TT) / 128), 256>>>(ctx, Wih, bih);
    k_seq<<<GRID, NTHR>>>(Whh, bhh, W1, b1, W2, b2, out);
}